// round 3
// baseline (speedup 1.0000x reference)
#include <cuda_runtime.h>

// Fully fused MPSLayer:
//   out[b,:] = (prod_t x[b,t]) * w + bias,  w = 1^T * (A_0...A_{D-1}) * P
// One kernel. Blocks 0..nprod-1 compute the matrix-chain tree (via atomic
// counters + flag), overlapped with the HBM-bound per-row product streaming
// done by all blocks. A memset node resets the sync words each graph replay.

#define R   16
#define RR  256
#define TS  20          // padded row stride for transposed tiles
#define CHUNK 16
#define MAXG  16
#define ROWS_PER_BLK 4  // 8 warps = 2 warps per row

__device__ float g_part1[256 * RR];
__device__ float g_part2[MAXG * RR];
__device__ float g_w[4096];
__device__ int   g_sync[MAXG + 2];  // [0..MAXG-1] group cnts, [MAXG] lvl2 cnt, [MAXG+1] flag

struct SmemT {
    float S[CHUNK - 1][R * TS];   // transposed operand tiles
    float M[2][RR];               // double-buffered running product
    float u[R];
    float p[8];                   // per-warp half-row products
    int   rank;
};

// Ordered product of n (<=16) RxR matrices at base[0..n-1]; result in sm->M[ret].
__device__ __forceinline__ int chain_prod(const float* __restrict__ base, int n,
                                          SmemT* sm, int t, int i, int j) {
    __syncthreads();
    for (int s = 1; s < n; ++s)   // prefetch transposed (coalesced, MLP=n-1)
        sm->S[s - 1][(t & 15) * TS + (t >> 4)] = base[(size_t)s * RR + t];
    sm->M[0][t] = base[t];
    __syncthreads();
    int cur = 0;
    for (int s = 1; s < n; ++s) {
        const float4* mrow = (const float4*)&sm->M[cur][i * R];
        const float4* bcol = (const float4*)&sm->S[s - 1][j * TS];
        float4 a0 = mrow[0], a1 = mrow[1], a2 = mrow[2], a3 = mrow[3];
        float4 b0 = bcol[0], b1 = bcol[1], b2 = bcol[2], b3 = bcol[3];
        float acc = a0.x * b0.x;
        acc = fmaf(a0.y, b0.y, acc); acc = fmaf(a0.z, b0.z, acc); acc = fmaf(a0.w, b0.w, acc);
        acc = fmaf(a1.x, b1.x, acc); acc = fmaf(a1.y, b1.y, acc);
        acc = fmaf(a1.z, b1.z, acc); acc = fmaf(a1.w, b1.w, acc);
        acc = fmaf(a2.x, b2.x, acc); acc = fmaf(a2.y, b2.y, acc);
        acc = fmaf(a2.z, b2.z, acc); acc = fmaf(a2.w, b2.w, acc);
        acc = fmaf(a3.x, b3.x, acc); acc = fmaf(a3.y, b3.y, acc);
        acc = fmaf(a3.z, b3.z, acc); acc = fmaf(a3.w, b3.w, acc);
        sm->M[cur ^ 1][t] = acc;
        cur ^= 1;
        __syncthreads();
    }
    return cur;
}

__global__ __launch_bounds__(256, 8)
void mps_fused(const float* __restrict__ x, const float* __restrict__ cores,
               const float* __restrict__ proj, const float* __restrict__ bias,
               float* __restrict__ out, int B, int D, int O,
               int nprod, int ngrp) {
    __shared__ SmemT sm;
    const int t = threadIdx.x;
    const int i = t >> 4, j = t & 15;

    // ---------- chain producer path (blocks 0..nprod-1) ----------
    if ((int)blockIdx.x < nprod) {
        const int start = blockIdx.x * CHUNK;
        const int n = min(CHUNK, D - start);
        int cur = chain_prod(cores + (size_t)start * RR, n, &sm, t, i, j);
        g_part1[(size_t)blockIdx.x * RR + t] = sm.M[cur][t];
        __threadfence();
        const int grp = blockIdx.x >> 4;
        const int gsz = min(16, nprod - (grp << 4));
        if (t == 0) sm.rank = atomicAdd(&g_sync[grp], 1);
        __syncthreads();
        if (sm.rank == gsz - 1) {           // last of group -> level-2 reduce
            __threadfence();
            cur = chain_prod(g_part1 + (size_t)(grp << 4) * RR, gsz, &sm, t, i, j);
            g_part2[(size_t)grp * RR + t] = sm.M[cur][t];
            __threadfence();
            if (t == 0) sm.rank = atomicAdd(&g_sync[MAXG], 1);
            __syncthreads();
            if (sm.rank == ngrp - 1) {      // last group -> final reduce + w
                __threadfence();
                cur = chain_prod(g_part2, ngrp, &sm, t, i, j);
                if (t < R) {
                    float s = 0.0f;
#pragma unroll
                    for (int ii = 0; ii < R; ++ii) s += sm.M[cur][ii * R + t];
                    sm.u[t] = s;
                }
                __syncthreads();
                for (int o = t; o < O; o += 256) {
                    float s = 0.0f;
#pragma unroll
                    for (int k = 0; k < R; ++k)
                        s = fmaf(sm.u[k], proj[k * O + o], s);
                    g_w[o] = s;
                }
                __threadfence();
                __syncthreads();
                if (t == 0) atomicExch(&g_sync[MAXG + 1], 1);  // publish
            }
        }
    }

    // ---------- streaming path (all blocks): 2 warps per row ----------
    const int w = t >> 5, lane = t & 31;
    const int row = blockIdx.x * ROWS_PER_BLK + (w >> 1);
    const int half = w & 1;
    float p = 1.0f;
    if (row < B) {
        const int dh  = (D >> 1) & ~3;               // 16B-aligned split
        const int off = half ? dh : 0;
        const int len = half ? (D - dh) : dh;
        const float*  xr  = x + (size_t)row * D + off;
        const float4* xr4 = (const float4*)xr;
        const int n4 = len >> 2;
#pragma unroll 8
        for (int idx = lane; idx < n4; idx += 32) {
            float4 v = xr4[idx];
            p *= v.x * v.y * v.z * v.w;
        }
        for (int idx = (n4 << 2) + lane; idx < len; idx += 32)
            p *= xr[idx];
#pragma unroll
        for (int o = 16; o; o >>= 1)
            p *= __shfl_xor_sync(0xffffffffu, p, o);
    }
    if (lane == 0) sm.p[w] = p;

    // wait for w (almost always already published by now)
    if (t == 0) {
        volatile int* f = &g_sync[MAXG + 1];
        while (*f == 0) __nanosleep(64);
    }
    __syncthreads();
    __threadfence();

    if (half == 0 && row < B) {
        const float pf = sm.p[w] * sm.p[w + 1];
        float* orow = out + (size_t)row * O;
        if (pf == 0.0f) {
            for (int o = lane; o < O; o += 32) orow[o] = bias[o];
        } else {
            for (int o = lane; o < O; o += 32)
                orow[o] = fmaf(pf, g_w[o], bias[o]);
        }
    }
}

extern "C" void kernel_launch(void* const* d_in, const int* in_sizes, int n_in,
                              void* d_out, int out_size) {
    const float* x     = (const float*)d_in[0];  // (B, D)
    const float* cores = (const float*)d_in[1];  // (D, 16, 16)
    const float* proj  = (const float*)d_in[2];  // (16, O)
    const float* bias  = (const float*)d_in[3];  // (O,)
    float* out = (float*)d_out;                  // (B, O)

    const int D = in_sizes[1] / RR;
    const int B = in_sizes[0] / D;
    const int O = in_sizes[3];

    int nprod = (D + CHUNK - 1) / CHUNK;         // 128 for D=2048
    if (nprod > 256) nprod = 256;
    const int ngrp = (nprod + 15) / 16;          // 8

    void* sp;
    cudaGetSymbolAddress(&sp, g_sync);
    cudaMemsetAsync(sp, 0, sizeof(int) * (MAXG + 2));

    const int blocks_rows = (B + ROWS_PER_BLK - 1) / ROWS_PER_BLK;  // 2048
    const int grid = blocks_rows > nprod ? blocks_rows : nprod;

    mps_fused<<<grid, 256>>>(x, cores, proj, bias, out, B, D, O, nprod, ngrp);
}

// round 4
// speedup vs baseline: 1.2253x; 1.2253x over previous
#include <cuda_runtime.h>

// MPSLayer, fully overlapped:
//   out[b,:] = (prod_t x[b,t]) * w + bias,   w = 1^T * (A_0...A_{D-1}) * P
// Kernel 1 (fused, no intra-kernel waiting):
//   - blocks [0, nprod):        matrix-chain tree -> g_w   (atomic-elected reducers)
//   - blocks [nprod, nprod+NR): row products      -> g_p   (HBM-bound stream)
// Kernel 2 (combine): out = g_p * g_w + bias  (guarded for p==0).

#define R   16
#define RR  256
#define TS  20
#define CHUNK 16
#define MAXG  16

__device__ float g_part1[256 * RR];
__device__ float g_part2[MAXG * RR];
__device__ float g_w[4096];
__device__ float g_p[32768];
__device__ int   g_sync[MAXG + 1];   // [0..MAXG-1] group counters, [MAXG] lvl2 counter

struct SmemT {
    float S[CHUNK - 1][R * TS];
    float M[2][RR];
    float u[R];
    int   rank;
};

// Ordered product of n (<=16) RxR matrices at base; result in sm->M[ret].
__device__ __forceinline__ int chain_prod(const float* __restrict__ base, int n,
                                          SmemT* sm, int t, int i, int j) {
    __syncthreads();
    for (int s = 1; s < n; ++s)
        sm->S[s - 1][(t & 15) * TS + (t >> 4)] = base[(size_t)s * RR + t];
    sm->M[0][t] = base[t];
    __syncthreads();
    int cur = 0;
    for (int s = 1; s < n; ++s) {
        const float4* mrow = (const float4*)&sm->M[cur][i * R];
        const float4* bcol = (const float4*)&sm->S[s - 1][j * TS];
        float4 a0 = mrow[0], a1 = mrow[1], a2 = mrow[2], a3 = mrow[3];
        float4 b0 = bcol[0], b1 = bcol[1], b2 = bcol[2], b3 = bcol[3];
        float acc = a0.x * b0.x;
        acc = fmaf(a0.y, b0.y, acc); acc = fmaf(a0.z, b0.z, acc); acc = fmaf(a0.w, b0.w, acc);
        acc = fmaf(a1.x, b1.x, acc); acc = fmaf(a1.y, b1.y, acc);
        acc = fmaf(a1.z, b1.z, acc); acc = fmaf(a1.w, b1.w, acc);
        acc = fmaf(a2.x, b2.x, acc); acc = fmaf(a2.y, b2.y, acc);
        acc = fmaf(a2.z, b2.z, acc); acc = fmaf(a2.w, b2.w, acc);
        acc = fmaf(a3.x, b3.x, acc); acc = fmaf(a3.y, b3.y, acc);
        acc = fmaf(a3.z, b3.z, acc); acc = fmaf(a3.w, b3.w, acc);
        sm->M[cur ^ 1][t] = acc;
        cur ^= 1;
        __syncthreads();
    }
    return cur;
}

__global__ __launch_bounds__(256, 8)
void mps_fused(const float* __restrict__ x, const float* __restrict__ cores,
               const float* __restrict__ proj,
               int B, int D, int O, int nprod, int ngrp) {
    const int t = threadIdx.x;

    if ((int)blockIdx.x < nprod) {
        // ---------------- chain producer path (no one waits on us) ----------
        __shared__ SmemT sm;
        const int i = t >> 4, j = t & 15;
        const int start = blockIdx.x * CHUNK;
        const int n = min(CHUNK, D - start);
        int cur = chain_prod(cores + (size_t)start * RR, n, &sm, t, i, j);
        g_part1[(size_t)blockIdx.x * RR + t] = sm.M[cur][t];
        __threadfence();
        const int grp = blockIdx.x >> 4;
        const int gsz = min(16, nprod - (grp << 4));
        if (t == 0) sm.rank = atomicAdd(&g_sync[grp], 1);
        __syncthreads();
        if (sm.rank == gsz - 1) {
            __threadfence();
            cur = chain_prod(g_part1 + (size_t)(grp << 4) * RR, gsz, &sm, t, i, j);
            g_part2[(size_t)grp * RR + t] = sm.M[cur][t];
            __threadfence();
            if (t == 0) sm.rank = atomicAdd(&g_sync[MAXG], 1);
            __syncthreads();
            if (sm.rank == ngrp - 1) {
                __threadfence();
                cur = chain_prod(g_part2, ngrp, &sm, t, i, j);
                if (t < R) {
                    float s = 0.0f;
#pragma unroll
                    for (int ii = 0; ii < R; ++ii) s += sm.M[cur][ii * R + t];
                    sm.u[t] = s;
                }
                __syncthreads();
                for (int o = t; o < O; o += 256) {
                    float s = 0.0f;
#pragma unroll
                    for (int k = 0; k < R; ++k)
                        s = fmaf(sm.u[k], proj[k * O + o], s);
                    g_w[o] = s;
                }
                // reset counters for the next graph replay (we are provably last)
                if (t <= MAXG) g_sync[t] = 0;
            }
        }
        return;
    }

    // ---------------- streaming path: one warp per row -> g_p ----------------
    const int w = t >> 5, lane = t & 31;
    const int row = ((int)blockIdx.x - nprod) * 8 + w;
    if (row >= B) return;

    const float4* xr4 = (const float4*)(x + (size_t)row * D);
    const int n4 = D >> 2;
    float p = 1.0f;
#pragma unroll 8
    for (int idx = lane; idx < n4; idx += 32) {
        float4 v = xr4[idx];
        p *= v.x * v.y * v.z * v.w;
    }
    for (int idx = (n4 << 2) + lane; idx < D; idx += 32)
        p *= x[(size_t)row * D + idx];
#pragma unroll
    for (int o = 16; o; o >>= 1)
        p *= __shfl_xor_sync(0xffffffffu, p, o);
    if (lane == 0) g_p[row] = p;
}

__global__ void mps_combine(const float* __restrict__ bias,
                            float* __restrict__ out, int B, int O) {
    const int idx = blockIdx.x * blockDim.x + threadIdx.x;
    if (idx >= B * O) return;
    const int b = idx / O, o = idx - b * O;
    const float p = g_p[b];
    out[idx] = (p == 0.0f) ? bias[o] : fmaf(p, g_w[o], bias[o]);
}

extern "C" void kernel_launch(void* const* d_in, const int* in_sizes, int n_in,
                              void* d_out, int out_size) {
    const float* x     = (const float*)d_in[0];  // (B, D)
    const float* cores = (const float*)d_in[1];  // (D, 16, 16)
    const float* proj  = (const float*)d_in[2];  // (16, O)
    const float* bias  = (const float*)d_in[3];  // (O,)
    float* out = (float*)d_out;                  // (B, O)

    const int D = in_sizes[1] / RR;
    const int B = in_sizes[0] / D;
    const int O = in_sizes[3];

    int nprod = (D + CHUNK - 1) / CHUNK;         // 128 for D=2048
    if (nprod > 256) nprod = 256;
    const int ngrp = (nprod + 15) / 16;          // 8

    const int row_blocks = (B + 7) / 8;          // 1024 (8 warps/block, 1 row/warp)
    mps_fused<<<nprod + row_blocks, 256>>>(x, cores, proj, B, D, O, nprod, ngrp);

    const int total = B * O;
    mps_combine<<<(total + 255) / 256, 256>>>(bias, out, B, O);
}